// round 7
// baseline (speedup 1.0000x reference)
#include <cuda_runtime.h>

// ---------------- problem constants ----------------
#define GX 1504
#define GY 1504
#define GZ 40
#define MAXV 150000
#define MAXP 10
#define N_MAX 2097152

#define SLOTBITS 22
#define SLOTS (1 << SLOTBITS)
#define SLOTMASK (SLOTS - 1)
#define BIG 0x40000000                 // phase-1 value offset; vids always < BIG

#define KBITS 19
#define KSLOTS (1 << KBITS)            // kept-voxel table: 150K keys / 512K slots
#define KMASK (KSLOTS - 1)

// output layout: voxels | coors | num_points | voxel_num  (all as float32)
#define VOX_OFF  0
#define COOR_OFF 7500000
#define NP_OFF   7950000
#define VN_OFF   8100000

#define TPB    256
#define ELEMS  8
#define TILE   (TPB * ELEMS)                 // 2048 points per scan tile
#define NB_MAX ((N_MAX + TILE - 1) / TILE)   // 1024
#define M0     262144                        // head = 128 tiles
#define GRID   296                           // 2 CTAs/SM on 148 SMs -> all resident

// ---------------- device scratch ----------------
__device__ int g_key[SLOTS];                  // 0 = empty; else flat+1 (persists)
__device__ int g_val[SLOTS];                  // phase1: BIG+max(N-i); phase2: vid
__device__ int g_pflat[N_MAX];                // head slots (tail only in fallback)
__device__ unsigned long long g_tile[NB_MAX]; // lookback: (state<<32)|count
__device__ int g_sat;                         // 1 = head saturated MAXV voxels
__device__ int g_cnt[MAXV];
__device__ int g_idx[MAXV * MAXP];
__device__ unsigned long long g_kept[KSLOTS]; // (flat+1)<<32 | vid ; 0 = empty
__device__ unsigned g_bar_arrive;             // global barrier state
__device__ unsigned g_bar_gen;

__device__ __forceinline__ unsigned hash_flat(int flat) {
    return ((unsigned)flat * 2654435761u) >> (32 - SLOTBITS);
}
__device__ __forceinline__ unsigned hash_kept(int flat) {
    return ((unsigned)flat * 0x9E3779B9u) >> (32 - KBITS);
}

// sense-reversing global barrier; safe because all GRID blocks are co-resident
__device__ __forceinline__ void gbar(unsigned nb) {
    __syncthreads();
    if (threadIdx.x == 0) {
        __threadfence();
        unsigned gen = *((volatile unsigned*)&g_bar_gen);
        if (atomicAdd(&g_bar_arrive, 1u) == nb - 1u) {
            g_bar_arrive = 0u;
            __threadfence();
            atomicAdd(&g_bar_gen, 1u);
        } else {
            while (*((volatile unsigned*)&g_bar_gen) == gen) __nanosleep(40);
        }
        __threadfence();
    }
    __syncthreads();
}

// XLA-exact binning: fp32 sub, then multiply by compile-time fp32 reciprocal.
__device__ __forceinline__ int bin3(float x, float y, float z, int* flat) {
    const float rx = 1.0f / 0.1f;    // == 10.0f exactly
    const float rz = 1.0f / 0.15f;   // 0x40D55555
    int cx = (int)floorf(__fmul_rn(__fadd_rn(x, 75.2f), rx));
    int cy = (int)floorf(__fmul_rn(__fadd_rn(y, 75.2f), rx));
    int cz = (int)floorf(__fmul_rn(__fadd_rn(z, 2.0f), rz));
    if (cx < 0 || cx >= GX || cy < 0 || cy >= GY || cz < 0 || cz >= GZ) return 0;
    *flat = (cz * GY + cy) * GX + cx;
    return 1;
}

__device__ __forceinline__ unsigned claim_slot(int flat) {
    int tag = flat + 1;
    unsigned h = hash_flat(flat);
    volatile int* vkey = (volatile int*)g_key;
    for (;;) {
        int k = vkey[h];
        if (k == tag) break;                 // warm replays: no CAS
        if (k == 0) {
            int old = atomicCAS(&g_key[h], 0, tag);
            if (old == 0 || old == tag) break;
        }
        h = (h + 1) & SLOTMASK;
    }
    return h;
}

// ---------------- fused tile: flags + lookback scan + assign + slot ------------
__device__ __forceinline__ void fused_tile(int tile, int lo, int hi, int N,
                                           int last_tile, float* __restrict__ out,
                                           bool build_kept,
                                           int* s_warp, int* s_prefix) {
    int base = tile * TILE + threadIdx.x * ELEMS;

    volatile int* vval = (volatile int*)g_val;
    int pf[ELEMS];
    unsigned fmask = 0;
    int s = 0;
#pragma unroll
    for (int k = 0; k < ELEMS; k++) {
        int i = base + k;
        pf[k] = (i >= lo && i < hi) ? g_pflat[i] : -1;
        if (pf[k] >= 0 && vval[pf[k]] == BIG + (N - i)) {
            fmask |= 1u << k;
            s++;
        }
    }

    int lane = threadIdx.x & 31, wid = threadIdx.x >> 5;
    int x = s;
#pragma unroll
    for (int o = 1; o < 32; o <<= 1) {
        int y = __shfl_up_sync(0xFFFFFFFFu, x, o);
        if (lane >= o) x += y;
    }
    if (lane == 31) s_warp[wid] = x;
    __syncthreads();
    if (wid == 0) {
        int w = (lane < 8) ? s_warp[lane] : 0;
#pragma unroll
        for (int o = 1; o < 8; o <<= 1) {
            int y = __shfl_up_sync(0xFFFFFFFFu, w, o);
            if (lane >= o) w += y;
        }
        if (lane < 8) s_warp[lane] = w;
    }
    __syncthreads();
    int total = s_warp[7];
    int texcl = x - s + (wid > 0 ? s_warp[wid - 1] : 0);

    if (threadIdx.x == 0)
        *((volatile unsigned long long*)&g_tile[tile]) = (1ULL << 32) | (unsigned)total;

    if (wid == 0) {
        int excl = 0;
        int look = tile - 1;
        while (look >= 0) {
            int idx = look - lane;
            unsigned long long p = (idx >= 0)
                ? *((volatile unsigned long long*)&g_tile[idx])
                : (2ULL << 32);
            int st = (int)(p >> 32);
            int val = (int)(p & 0xFFFFFFFFULL);
            unsigned bp = __ballot_sync(0xFFFFFFFFu, st == 2);
            unsigned bn = __ballot_sync(0xFFFFFFFFu, st == 0);
            if (bp) {
                int j = __ffs(bp) - 1;
                unsigned need = j ? ((1u << j) - 1u) : 0u;
                if ((bn & need) == 0) {
                    int c = (lane <= j) ? val : 0;
#pragma unroll
                    for (int o = 16; o > 0; o >>= 1) c += __shfl_down_sync(0xFFFFFFFFu, c, o);
                    excl += __shfl_sync(0xFFFFFFFFu, c, 0);
                    break;
                }
            } else if (bn == 0) {
                int c = val;
#pragma unroll
                for (int o = 16; o > 0; o >>= 1) c += __shfl_down_sync(0xFFFFFFFFu, c, o);
                excl += __shfl_sync(0xFFFFFFFFu, c, 0);
                look -= 32;
            }
        }
        if (lane == 0) {
            int tot = excl + total;
            *((volatile unsigned long long*)&g_tile[tile]) = (2ULL << 32) | (unsigned)tot;
            *s_prefix = excl;
            if (tile == last_tile) {
                if (build_kept) {
                    if (tot >= MAXV || hi >= N) {    // saturated or head covers all
                        g_sat = 1;
                        out[VN_OFF] = (float)(tot < MAXV ? tot : MAXV);
                    }
                } else {
                    out[VN_OFF] = (float)(tot < MAXV ? tot : MAXV);
                }
            }
        }
    }
    __syncthreads();

    int vid = *s_prefix + texcl;
    int myvid[ELEMS];
#pragma unroll
    for (int k = 0; k < ELEMS; k++) {
        myvid[k] = -1;
        if (fmask & (1u << k)) {
            int slot = pf[k];
            int flat = ((volatile int*)g_key)[slot] - 1;
            vval[slot] = vid;
            if (vid < MAXV) {
                int cx = flat % GX;
                int r = flat / GX;
                int cy = r % GY;
                int cz = r / GY;
                out[COOR_OFF + (size_t)vid * 3 + 0] = (float)cz;
                out[COOR_OFF + (size_t)vid * 3 + 1] = (float)cy;
                out[COOR_OFF + (size_t)vid * 3 + 2] = (float)cx;
                if (build_kept) {
                    unsigned long long ent =
                        ((unsigned long long)(unsigned)(flat + 1) << 32) | (unsigned)vid;
                    unsigned h2 = hash_kept(flat);
                    volatile unsigned long long* vk = (volatile unsigned long long*)g_kept;
                    for (;;) {
                        unsigned long long cur = vk[h2];
                        if ((unsigned)(cur >> 32) == (unsigned)(flat + 1)) break; // stale==new
                        if (cur == 0ULL) {
                            unsigned long long old = atomicCAS(&g_kept[h2], 0ULL, ent);
                            if (old == 0ULL ||
                                (unsigned)(old >> 32) == (unsigned)(flat + 1)) break;
                        }
                        h2 = (h2 + 1) & KMASK;
                    }
                }
            }
            myvid[k] = vid;
            vid++;
        }
    }
    __threadfence();
    __syncthreads();

#pragma unroll
    for (int k = 0; k < ELEMS; k++) {
        int i = base + k;
        if (i < lo || i >= hi || pf[k] < 0) continue;
        int v = myvid[k];
        if (v < 0) {
            v = vval[pf[k]];
            while (v >= BIG) { __nanosleep(60); v = vval[pf[k]]; }
        }
        if (v < MAXV) {
            int sl = atomicAdd(&g_cnt[v], 1);
            if (sl < MAXP) g_idx[v * MAXP + sl] = i;
        }
    }
}

// ---------------- the single persistent kernel ----------------
#define TELEMS 4
__global__ void __launch_bounds__(TPB) vox_all(const float* __restrict__ pts,
                                               int N, int Nh, int nb_head,
                                               int nb_total,
                                               float* __restrict__ out) {
    __shared__ float srow[TPB * 50];        // 50 KB -> 2 CTAs/SM, all GRID resident
    __shared__ int s_warp[8];
    __shared__ int s_prefix;

    const unsigned NB = gridDim.x;
    int tid = blockIdx.x * TPB + threadIdx.x;
    int gsz = NB * TPB;

    // ---- phase 0: init + head bin/claim/atomicMax ----
    for (int i = tid; i < NB_MAX; i += gsz) g_tile[i] = 0ULL;
    if (tid == 0) g_sat = 0;
    for (int i = tid; i < MAXV; i += gsz) g_cnt[i] = 0;
    for (int i = tid; i < Nh; i += gsz) {
        float x = pts[(size_t)i * 5 + 0];
        float y = pts[(size_t)i * 5 + 1];
        float z = pts[(size_t)i * 5 + 2];
        int flat;
        if (!bin3(x, y, z, &flat)) { g_pflat[i] = -1; continue; }
        unsigned h = claim_slot(flat);
        atomicMax(&g_val[h], BIG + (N - i));    // stale vid (<BIG) always dominated
        g_pflat[i] = (int)h;
    }
    gbar(NB);

    // ---- phase 1: fused head (block b = tile b; all tiles concurrent) ----
    if ((int)blockIdx.x < nb_head)
        fused_tile(blockIdx.x, 0, Nh, N, nb_head - 1, out, true, s_warp, &s_prefix);
    gbar(NB);

    int sat = *((volatile int*)&g_sat);

    // ---- phase 2: tail membership stream (warp-batched grid-stride) ----
    if (N > Nh) {
        int nchunks = (N - Nh + 32 * TELEMS - 1) / (32 * TELEMS);
        int gw = tid >> 5;
        int lane = threadIdx.x & 31;
        int nwarp = gsz >> 5;
        for (int ch = gw; ch < nchunks; ch += nwarp) {
            int base = Nh + ch * (32 * TELEMS) + lane;
            float px[TELEMS], py[TELEMS], pz[TELEMS];
            int ok[TELEMS], flat[TELEMS];
#pragma unroll
            for (int k = 0; k < TELEMS; k++) {
                int i = base + k * 32;
                ok[k] = (i < N);
                if (ok[k]) {
                    px[k] = __ldg(pts + (size_t)i * 5 + 0);
                    py[k] = __ldg(pts + (size_t)i * 5 + 1);
                    pz[k] = __ldg(pts + (size_t)i * 5 + 2);
                }
            }
#pragma unroll
            for (int k = 0; k < TELEMS; k++)
                if (ok[k]) ok[k] = bin3(px[k], py[k], pz[k], &flat[k]);

            if (sat) {
                unsigned h[TELEMS];
                unsigned long long e[TELEMS];
#pragma unroll
                for (int k = 0; k < TELEMS; k++) {
                    if (ok[k]) {
                        h[k] = hash_kept(flat[k]);
                        e[k] = g_kept[h[k]];                  // batched first probes
                    }
                }
#pragma unroll
                for (int k = 0; k < TELEMS; k++) {
                    if (!ok[k]) continue;
                    unsigned tag = (unsigned)(flat[k] + 1);
                    unsigned hh = h[k];
                    unsigned long long cur = e[k];
                    for (;;) {
                        if (cur == 0ULL) break;               // voxel not kept
                        if ((unsigned)(cur >> 32) == tag) {
                            int v = (int)(unsigned)(cur & 0xFFFFFFFFULL);
                            int i = base + k * 32;
                            int sl = atomicAdd(&g_cnt[v], 1);
                            if (sl < MAXP) g_idx[v * MAXP + sl] = i;
                            break;
                        }
                        hh = (hh + 1) & KMASK;
                        cur = g_kept[hh];
                    }
                }
            } else {
                // fallback: continue full pipeline (phase 2b consumes)
#pragma unroll
                for (int k = 0; k < TELEMS; k++) {
                    int i = base + k * 32;
                    if (i >= N) continue;
                    if (!ok[k]) { g_pflat[i] = -1; continue; }
                    unsigned hh = claim_slot(flat[k]);
                    atomicMax(&g_val[hh], BIG + (N - i));
                    g_pflat[i] = (int)hh;
                }
            }
        }
        if (!sat) {
            gbar(NB);
            // phase 2b (fallback): fused tail tiles, block-strided (lookback only
            // ever waits on same-iteration or completed tiles -> no deadlock)
            for (int t = nb_head + (int)blockIdx.x; t < nb_total; t += (int)NB)
                fused_tile(t, Nh, N, N, nb_total - 1, out, false, s_warp, &s_prefix);
        }
    }
    gbar(NB);

    // ---- phase 3: emit (block-strided 256-voxel tiles, smem-staged stores) ----
    int ntiles = (MAXV + TPB - 1) / TPB;
    for (int t = (int)blockIdx.x; t < ntiles; t += (int)NB) {
        __syncthreads();                       // srow reuse guard
        int vid = t * TPB + threadIdx.x;
        if (vid < MAXV) {
            int c = g_cnt[vid];
            int m = c < MAXP ? c : MAXP;
            int a[MAXP];
            for (int k = 0; k < m; k++) a[k] = g_idx[vid * MAXP + k];
            for (int k = 1; k < m; k++) {      // restores deterministic point order
                int v = a[k];
                int j = k - 1;
                while (j >= 0 && a[j] > v) { a[j + 1] = a[j]; j--; }
                a[j + 1] = v;
            }
            float* row = srow + threadIdx.x * 50;
#pragma unroll
            for (int q = 0; q < 50; q++) row[q] = 0.0f;
            for (int k = 0; k < m; k++) {
                const float* p = pts + (size_t)a[k] * 5;
                row[k * 5 + 0] = __ldg(p + 0);
                row[k * 5 + 1] = __ldg(p + 1);
                row[k * 5 + 2] = __ldg(p + 2);
                row[k * 5 + 3] = __ldg(p + 3);
                row[k * 5 + 4] = __ldg(p + 4);
            }
            out[NP_OFF + vid] = (float)m;
            if (m == 0) {                      // invalid slot -> coors = -1
                out[COOR_OFF + (size_t)vid * 3 + 0] = -1.0f;
                out[COOR_OFF + (size_t)vid * 3 + 1] = -1.0f;
                out[COOR_OFF + (size_t)vid * 3 + 2] = -1.0f;
            }
        }
        __syncthreads();
        int rows = MAXV - t * TPB;
        if (rows > TPB) rows = TPB;
        int nf4 = rows * 50 / 4;               // rows even -> divisible by 4
        const float4* s4 = (const float4*)srow;
        float4* o4 = (float4*)(out + VOX_OFF + (size_t)t * TPB * 50);
        for (int j = threadIdx.x; j < nf4; j += TPB) o4[j] = s4[j];
    }
}

// ---------------- launch ----------------
extern "C" void kernel_launch(void* const* d_in, const int* in_sizes, int n_in,
                              void* d_out, int out_size) {
    const float* pts = (const float*)d_in[0];
    int N = in_sizes[0] / 5;
    if (N > N_MAX) N = N_MAX;
    float* out = (float*)d_out;

    int Nh = N < M0 ? N : M0;
    int nb_head = (Nh + TILE - 1) / TILE;
    int nb_total = (N + TILE - 1) / TILE;

    vox_all<<<GRID, TPB>>>(pts, N, Nh, nb_head, nb_total, out);
}

// round 8
// speedup vs baseline: 1.3667x; 1.3667x over previous
#include <cuda_runtime.h>

// ---------------- problem constants ----------------
#define GX 1504
#define GY 1504
#define GZ 40
#define MAXV 150000
#define MAXP 10
#define N_MAX 2097152

#define SLOTBITS 22
#define SLOTS (1 << SLOTBITS)
#define SLOTMASK (SLOTS - 1)
#define BIG 0x40000000                 // phase-1 value offset; vids always < BIG

#define KBITS 19
#define KSLOTS (1 << KBITS)            // kept-voxel table: 150K keys / 512K slots
#define KMASK (KSLOTS - 1)

// output layout: voxels | coors | num_points | voxel_num  (all as float32)
#define VOX_OFF  0
#define COOR_OFF 7500000
#define NP_OFF   7950000
#define VN_OFF   8100000

#define TPB    256
#define ELEMS  8
#define TILE   (TPB * ELEMS)                 // 2048 points per scan tile
#define NB_MAX ((N_MAX + TILE - 1) / TILE)   // 1024
#define M0     180224                        // head = 88 tiles; E[distinct]≈179.8K >> 150K
#define HGRID  296                           // head kernel: 2 CTAs/SM, co-resident
#define TGRID  888                           // tail kernel: 6 CTAs/SM via launch_bounds

// ---------------- device scratch ----------------
__device__ int g_key[SLOTS];                  // 0 = empty; else flat+1 (persists)
__device__ int g_val[SLOTS];                  // phase1: BIG+max(N-i); phase2: vid
__device__ int g_pflat[N_MAX];                // head slots (tail only in fallback)
__device__ unsigned long long g_tile[NB_MAX]; // lookback: (state<<32)|count
__device__ int g_sat;                         // 1 = head saturated MAXV voxels
__device__ int g_cnt[MAXV];
__device__ int g_idx[MAXV * MAXP];
__device__ unsigned long long g_kept[KSLOTS]; // (flat+1)<<32 | vid ; 0 = empty
__device__ unsigned g_bar_arrive;             // global barrier state
__device__ unsigned g_bar_gen;

__device__ __forceinline__ unsigned hash_flat(int flat) {
    return ((unsigned)flat * 2654435761u) >> (32 - SLOTBITS);
}
__device__ __forceinline__ unsigned hash_kept(int flat) {
    return ((unsigned)flat * 0x9E3779B9u) >> (32 - KBITS);
}

// sense-reversing global barrier; caller guarantees all nb blocks co-resident
__device__ __forceinline__ void gbar(unsigned nb) {
    __syncthreads();
    if (threadIdx.x == 0) {
        __threadfence();
        unsigned gen = *((volatile unsigned*)&g_bar_gen);
        if (atomicAdd(&g_bar_arrive, 1u) == nb - 1u) {
            g_bar_arrive = 0u;
            __threadfence();
            atomicAdd(&g_bar_gen, 1u);
        } else {
            while (*((volatile unsigned*)&g_bar_gen) == gen) __nanosleep(40);
        }
        __threadfence();
    }
    __syncthreads();
}

// XLA-exact binning: fp32 sub, then multiply by compile-time fp32 reciprocal.
__device__ __forceinline__ int bin3(float x, float y, float z, int* flat) {
    const float rx = 1.0f / 0.1f;    // == 10.0f exactly
    const float rz = 1.0f / 0.15f;   // 0x40D55555
    int cx = (int)floorf(__fmul_rn(__fadd_rn(x, 75.2f), rx));
    int cy = (int)floorf(__fmul_rn(__fadd_rn(y, 75.2f), rx));
    int cz = (int)floorf(__fmul_rn(__fadd_rn(z, 2.0f), rz));
    if (cx < 0 || cx >= GX || cy < 0 || cy >= GY || cz < 0 || cz >= GZ) return 0;
    *flat = (cz * GY + cy) * GX + cx;
    return 1;
}

__device__ __forceinline__ unsigned claim_slot(int flat) {
    int tag = flat + 1;
    unsigned h = hash_flat(flat);
    volatile int* vkey = (volatile int*)g_key;
    for (;;) {
        int k = vkey[h];
        if (k == tag) break;                 // warm replays: no CAS
        if (k == 0) {
            int old = atomicCAS(&g_key[h], 0, tag);
            if (old == 0 || old == tag) break;
        }
        h = (h + 1) & SLOTMASK;
    }
    return h;
}

// ---------------- fused tile: flags + lookback scan + assign + slot ------------
__device__ void fused_tile(int tile, int lo, int hi, int N,
                           int last_tile, float* __restrict__ out,
                           bool build_kept) {
    __shared__ int s_warp[8];
    __shared__ int s_prefix;

    int base = tile * TILE + threadIdx.x * ELEMS;

    volatile int* vval = (volatile int*)g_val;
    int pf[ELEMS];
    unsigned fmask = 0;
    int s = 0;
#pragma unroll
    for (int k = 0; k < ELEMS; k++) {
        int i = base + k;
        pf[k] = (i >= lo && i < hi) ? g_pflat[i] : -1;
        if (pf[k] >= 0 && vval[pf[k]] == BIG + (N - i)) {
            fmask |= 1u << k;
            s++;
        }
    }

    int lane = threadIdx.x & 31, wid = threadIdx.x >> 5;
    int x = s;
#pragma unroll
    for (int o = 1; o < 32; o <<= 1) {
        int y = __shfl_up_sync(0xFFFFFFFFu, x, o);
        if (lane >= o) x += y;
    }
    if (lane == 31) s_warp[wid] = x;
    __syncthreads();
    if (wid == 0) {
        int w = (lane < 8) ? s_warp[lane] : 0;
#pragma unroll
        for (int o = 1; o < 8; o <<= 1) {
            int y = __shfl_up_sync(0xFFFFFFFFu, w, o);
            if (lane >= o) w += y;
        }
        if (lane < 8) s_warp[lane] = w;
    }
    __syncthreads();
    int total = s_warp[7];
    int texcl = x - s + (wid > 0 ? s_warp[wid - 1] : 0);

    if (threadIdx.x == 0)
        *((volatile unsigned long long*)&g_tile[tile]) = (1ULL << 32) | (unsigned)total;

    if (wid == 0) {
        int excl = 0;
        int look = tile - 1;
        while (look >= 0) {
            int idx = look - lane;
            unsigned long long p = (idx >= 0)
                ? *((volatile unsigned long long*)&g_tile[idx])
                : (2ULL << 32);
            int st = (int)(p >> 32);
            int val = (int)(p & 0xFFFFFFFFULL);
            unsigned bp = __ballot_sync(0xFFFFFFFFu, st == 2);
            unsigned bn = __ballot_sync(0xFFFFFFFFu, st == 0);
            if (bp) {
                int j = __ffs(bp) - 1;
                unsigned need = j ? ((1u << j) - 1u) : 0u;
                if ((bn & need) == 0) {
                    int c = (lane <= j) ? val : 0;
#pragma unroll
                    for (int o = 16; o > 0; o >>= 1) c += __shfl_down_sync(0xFFFFFFFFu, c, o);
                    excl += __shfl_sync(0xFFFFFFFFu, c, 0);
                    break;
                }
            } else if (bn == 0) {
                int c = val;
#pragma unroll
                for (int o = 16; o > 0; o >>= 1) c += __shfl_down_sync(0xFFFFFFFFu, c, o);
                excl += __shfl_sync(0xFFFFFFFFu, c, 0);
                look -= 32;
            }
        }
        if (lane == 0) {
            int tot = excl + total;
            *((volatile unsigned long long*)&g_tile[tile]) = (2ULL << 32) | (unsigned)tot;
            s_prefix = excl;
            if (tile == last_tile) {
                if (build_kept) {
                    if (tot >= MAXV || hi >= N) {    // saturated or head covers all
                        g_sat = 1;
                        out[VN_OFF] = (float)(tot < MAXV ? tot : MAXV);
                    }
                } else {
                    out[VN_OFF] = (float)(tot < MAXV ? tot : MAXV);
                }
            }
        }
    }
    __syncthreads();

    int vid = s_prefix + texcl;
    int myvid[ELEMS];
#pragma unroll
    for (int k = 0; k < ELEMS; k++) {
        myvid[k] = -1;
        if (fmask & (1u << k)) {
            int slot = pf[k];
            int flat = ((volatile int*)g_key)[slot] - 1;
            vval[slot] = vid;
            if (vid < MAXV) {
                int cx = flat % GX;
                int r = flat / GX;
                int cy = r % GY;
                int cz = r / GY;
                out[COOR_OFF + (size_t)vid * 3 + 0] = (float)cz;
                out[COOR_OFF + (size_t)vid * 3 + 1] = (float)cy;
                out[COOR_OFF + (size_t)vid * 3 + 2] = (float)cx;
                if (build_kept) {
                    unsigned long long ent =
                        ((unsigned long long)(unsigned)(flat + 1) << 32) | (unsigned)vid;
                    unsigned h2 = hash_kept(flat);
                    volatile unsigned long long* vk = (volatile unsigned long long*)g_kept;
                    for (;;) {
                        unsigned long long cur = vk[h2];
                        if ((unsigned)(cur >> 32) == (unsigned)(flat + 1)) break; // stale==new
                        if (cur == 0ULL) {
                            unsigned long long old = atomicCAS(&g_kept[h2], 0ULL, ent);
                            if (old == 0ULL ||
                                (unsigned)(old >> 32) == (unsigned)(flat + 1)) break;
                        }
                        h2 = (h2 + 1) & KMASK;
                    }
                }
            }
            myvid[k] = vid;
            vid++;
        }
    }
    __threadfence();
    __syncthreads();

#pragma unroll
    for (int k = 0; k < ELEMS; k++) {
        int i = base + k;
        if (i < lo || i >= hi || pf[k] < 0) continue;
        int v = myvid[k];
        if (v < 0) {
            v = vval[pf[k]];
            while (v >= BIG) { __nanosleep(60); v = vval[pf[k]]; }
        }
        if (v < MAXV) {
            int sl = atomicAdd(&g_cnt[v], 1);
            if (sl < MAXP) g_idx[v * MAXP + sl] = i;
        }
    }
}

// ---------------- kernel 1: head — init + bin + barrier + fused tiles ----------
__global__ void __launch_bounds__(TPB) vox_head(const float* __restrict__ pts,
                                                int N, int Nh, int nb_head,
                                                float* __restrict__ out) {
    int tid = blockIdx.x * TPB + threadIdx.x;
    int gsz = gridDim.x * TPB;

    for (int i = tid; i < NB_MAX; i += gsz) g_tile[i] = 0ULL;
    if (tid == 0) g_sat = 0;
    for (int i = tid; i < MAXV; i += gsz) g_cnt[i] = 0;
    for (int i = tid; i < Nh; i += gsz) {
        float x = pts[(size_t)i * 5 + 0];
        float y = pts[(size_t)i * 5 + 1];
        float z = pts[(size_t)i * 5 + 2];
        int flat;
        if (!bin3(x, y, z, &flat)) { g_pflat[i] = -1; continue; }
        unsigned h = claim_slot(flat);
        atomicMax(&g_val[h], BIG + (N - i));    // stale vid (<BIG) always dominated
        g_pflat[i] = (int)h;
    }
    gbar(gridDim.x);

    if ((int)blockIdx.x < nb_head)
        fused_tile(blockIdx.x, 0, Nh, N, nb_head - 1, out, true);
}

// ---------------- kernel 2: tail — membership stream (+ in-kernel fallback) ----
#define TELEMS 4
__global__ void __launch_bounds__(TPB, 6) vox_tail(const float* __restrict__ pts,
                                                   int N, int Nh, int nb_head,
                                                   int nb_total,
                                                   float* __restrict__ out) {
    int sat = *((volatile int*)&g_sat);
    int tid = blockIdx.x * TPB + threadIdx.x;
    int gsz = gridDim.x * TPB;
    int lane = threadIdx.x & 31;
    int nwarp = gsz >> 5;
    int gw = tid >> 5;
    int nchunks = (N - Nh + 32 * TELEMS - 1) / (32 * TELEMS);

    for (int ch = gw; ch < nchunks; ch += nwarp) {
        int base = Nh + ch * (32 * TELEMS) + lane;
        float px[TELEMS], py[TELEMS], pz[TELEMS];
        int ok[TELEMS], flat[TELEMS];
#pragma unroll
        for (int k = 0; k < TELEMS; k++) {
            int i = base + k * 32;
            ok[k] = (i < N);
            if (ok[k]) {
                px[k] = __ldg(pts + (size_t)i * 5 + 0);
                py[k] = __ldg(pts + (size_t)i * 5 + 1);
                pz[k] = __ldg(pts + (size_t)i * 5 + 2);
            }
        }
#pragma unroll
        for (int k = 0; k < TELEMS; k++)
            if (ok[k]) ok[k] = bin3(px[k], py[k], pz[k], &flat[k]);

        if (sat) {
            unsigned h[TELEMS];
            unsigned long long e[TELEMS];
#pragma unroll
            for (int k = 0; k < TELEMS; k++) {
                if (ok[k]) {
                    h[k] = hash_kept(flat[k]);
                    e[k] = g_kept[h[k]];                  // batched first probes
                }
            }
#pragma unroll
            for (int k = 0; k < TELEMS; k++) {
                if (!ok[k]) continue;
                unsigned tag = (unsigned)(flat[k] + 1);
                unsigned hh = h[k];
                unsigned long long cur = e[k];
                for (;;) {
                    if (cur == 0ULL) break;               // voxel not kept
                    if ((unsigned)(cur >> 32) == tag) {
                        int v = (int)(unsigned)(cur & 0xFFFFFFFFULL);
                        int i = base + k * 32;
                        int sl = atomicAdd(&g_cnt[v], 1);
                        if (sl < MAXP) g_idx[v * MAXP + sl] = i;
                        break;
                    }
                    hh = (hh + 1) & KMASK;
                    cur = g_kept[hh];
                }
            }
        } else {
#pragma unroll
            for (int k = 0; k < TELEMS; k++) {
                int i = base + k * 32;
                if (i >= N) continue;
                if (!ok[k]) { g_pflat[i] = -1; continue; }
                unsigned hh = claim_slot(flat[k]);
                atomicMax(&g_val[hh], BIG + (N - i));
                g_pflat[i] = (int)hh;
            }
        }
    }

    if (!sat) {
        // fallback: finish the scan pipeline for tail tiles in-kernel.
        // All TGRID blocks co-resident (launch_bounds(256,6)) -> gbar safe; tile
        // waves are block-strided so lookback targets are concurrent or done.
        gbar(gridDim.x);
        for (int t = nb_head + (int)blockIdx.x; t < nb_total; t += (int)gridDim.x) {
            fused_tile(t, Nh, N, N, nb_total - 1, out, false);
            __syncthreads();
        }
    }
}

// ---------------- kernel 3: emit — smem staging, coalesced output -------------
__global__ void __launch_bounds__(TPB) vox_emit(const float* __restrict__ pts,
                                                float* __restrict__ out) {
    __shared__ float srow[TPB * 50];          // 50 KB
    int vid = blockIdx.x * TPB + threadIdx.x;
    if (vid < MAXV) {
        int c = g_cnt[vid];
        int m = c < MAXP ? c : MAXP;
        int a[MAXP];
        for (int k = 0; k < m; k++) a[k] = g_idx[vid * MAXP + k];
        for (int k = 1; k < m; k++) {         // restores deterministic point order
            int v = a[k];
            int j = k - 1;
            while (j >= 0 && a[j] > v) { a[j + 1] = a[j]; j--; }
            a[j + 1] = v;
        }
        float* row = srow + threadIdx.x * 50;
#pragma unroll
        for (int q = 0; q < 50; q++) row[q] = 0.0f;
        for (int k = 0; k < m; k++) {
            const float* p = pts + (size_t)a[k] * 5;
            row[k * 5 + 0] = __ldg(p + 0);
            row[k * 5 + 1] = __ldg(p + 1);
            row[k * 5 + 2] = __ldg(p + 2);
            row[k * 5 + 3] = __ldg(p + 3);
            row[k * 5 + 4] = __ldg(p + 4);
        }
        out[NP_OFF + vid] = (float)m;
        if (m == 0) {                          // invalid slot -> coors = -1
            out[COOR_OFF + (size_t)vid * 3 + 0] = -1.0f;
            out[COOR_OFF + (size_t)vid * 3 + 1] = -1.0f;
            out[COOR_OFF + (size_t)vid * 3 + 2] = -1.0f;
        }
    }
    __syncthreads();
    int rows = MAXV - blockIdx.x * TPB;
    if (rows > TPB) rows = TPB;
    int nf4 = rows * 50 / 4;                   // rows even -> divisible by 4
    const float4* s4 = (const float4*)srow;
    float4* o4 = (float4*)(out + VOX_OFF + (size_t)blockIdx.x * TPB * 50);
    for (int j = threadIdx.x; j < nf4; j += TPB) o4[j] = s4[j];
}

// ---------------- launch ----------------
extern "C" void kernel_launch(void* const* d_in, const int* in_sizes, int n_in,
                              void* d_out, int out_size) {
    const float* pts = (const float*)d_in[0];
    int N = in_sizes[0] / 5;
    if (N > N_MAX) N = N_MAX;
    float* out = (float*)d_out;

    int Nh = N < M0 ? N : M0;
    int nb_head = (Nh + TILE - 1) / TILE;      // <= 88 <= HGRID
    int nb_total = (N + TILE - 1) / TILE;

    vox_head<<<HGRID, TPB>>>(pts, N, Nh, nb_head, out);
    if (N > Nh)
        vox_tail<<<TGRID, TPB>>>(pts, N, Nh, nb_head, nb_total, out);
    vox_emit<<<(MAXV + TPB - 1) / TPB, TPB>>>(pts, out);
}

// round 9
// speedup vs baseline: 1.9956x; 1.4602x over previous
#include <cuda_runtime.h>

// ---------------- problem constants ----------------
#define GX 1504
#define GY 1504
#define GZ 40
#define MAXV 150000
#define MAXP 10
#define N_MAX 2097152

#define SLOTBITS 22
#define SLOTS (1 << SLOTBITS)
#define SLOTMASK (SLOTS - 1)
#define BIG 0x40000000u                // phase-1 low32 offset; vids always < BIG

#define KBITS 19
#define KSLOTS (1 << KBITS)            // kept-voxel table: 150K keys / 512K slots
#define KMASK (KSLOTS - 1)

// output layout: voxels | coors | num_points | voxel_num  (all as float32)
#define VOX_OFF  0
#define COOR_OFF 7500000
#define NP_OFF   7950000
#define VN_OFF   8100000

#define TPB    256
#define ELEMS  2
#define TILE   (TPB * ELEMS)                 // 512 points per scan tile
#define NB_MAX ((N_MAX + TILE - 1) / TILE)   // 4096
#define M0     180224                        // head: 352 tiles; E[distinct]≈179.8K >> 150K
#define HGRID  704                           // = M0/TPB; 5 CTAs/SM co-resident
#define TGRID  888                           // tail: 6 CTAs/SM co-resident

// ---------------- device scratch ----------------
// Packed table entry: high32 = flat+1 (key), low32 = BIG+(N-i) then vid.
// Persists across graph replays: stale (key|vid) is dominated by BIG-offset atomicMax.
__device__ unsigned long long g_slot[SLOTS];  // 32 MB
__device__ int g_pflat[N_MAX];                // slot per point (head; tail in fallback)
__device__ unsigned long long g_tile[NB_MAX]; // lookback: (state<<32)|count
__device__ int g_sat;                         // 1 = head saturated MAXV voxels
__device__ int g_cnt[MAXV];
__device__ int g_idx[MAXV * MAXP];
__device__ unsigned long long g_kept[KSLOTS]; // (flat+1)<<32 | vid ; 0 = empty
__device__ unsigned g_bar_arrive;
__device__ unsigned g_bar_gen;

__device__ __forceinline__ unsigned hash_flat(int flat) {
    return ((unsigned)flat * 2654435761u) >> (32 - SLOTBITS);
}
__device__ __forceinline__ unsigned hash_kept(int flat) {
    return ((unsigned)flat * 0x9E3779B9u) >> (32 - KBITS);
}

// sense-reversing global barrier; caller guarantees all nb blocks co-resident
__device__ __forceinline__ void gbar(unsigned nb) {
    __syncthreads();
    if (threadIdx.x == 0) {
        __threadfence();
        unsigned gen = *((volatile unsigned*)&g_bar_gen);
        if (atomicAdd(&g_bar_arrive, 1u) == nb - 1u) {
            g_bar_arrive = 0u;
            __threadfence();
            atomicAdd(&g_bar_gen, 1u);
        } else {
            while (*((volatile unsigned*)&g_bar_gen) == gen) __nanosleep(40);
        }
        __threadfence();
    }
    __syncthreads();
}

// XLA-exact binning: fp32 sub, then multiply by compile-time fp32 reciprocal.
__device__ __forceinline__ int bin3(float x, float y, float z, int* flat) {
    const float rx = 1.0f / 0.1f;    // == 10.0f exactly
    const float rz = 1.0f / 0.15f;   // 0x40D55555
    int cx = (int)floorf(__fmul_rn(__fadd_rn(x, 75.2f), rx));
    int cy = (int)floorf(__fmul_rn(__fadd_rn(y, 75.2f), rx));
    int cz = (int)floorf(__fmul_rn(__fadd_rn(z, 2.0f), rz));
    if (cx < 0 || cx >= GX || cy < 0 || cy >= GY || cz < 0 || cz >= GZ) return 0;
    *flat = (cz * GY + cy) * GX + cx;
    return 1;
}

// probe-claim-record in ONE random line: returns owned slot index
__device__ __forceinline__ unsigned claim_record(int flat, unsigned v) {
    unsigned tag = (unsigned)(flat + 1);
    unsigned long long ent = ((unsigned long long)tag << 32) | v;
    unsigned h = hash_flat(flat);
    volatile unsigned long long* vs = (volatile unsigned long long*)g_slot;
    for (;;) {
        unsigned long long cur = vs[h];
        if ((unsigned)(cur >> 32) == tag) {        // warm replays: single read
            atomicMax(&g_slot[h], ent);
            break;
        }
        if (cur == 0ULL) {
            unsigned long long old = atomicCAS(&g_slot[h], 0ULL, ent);
            if (old == 0ULL) break;
            if ((unsigned)(old >> 32) == tag) { atomicMax(&g_slot[h], ent); break; }
        }
        h = (h + 1) & SLOTMASK;
    }
    return h;
}

// ---------------- fused tile: flags + lookback scan + assign + slot ------------
__device__ void fused_tile(int tile, int lo, int hi, int N,
                           int last_tile, float* __restrict__ out,
                           bool build_kept) {
    __shared__ int s_warp[8];
    __shared__ int s_prefix;

    int base = tile * TILE + threadIdx.x * ELEMS;

    int pf[ELEMS];
    unsigned long long ee[ELEMS];
    unsigned fmask = 0;
    int s = 0;
#pragma unroll
    for (int k = 0; k < ELEMS; k++) {
        int i = base + k;
        pf[k] = (i >= lo && i < hi) ? g_pflat[i] : -1;
    }
#pragma unroll
    for (int k = 0; k < ELEMS; k++)            // plain loads -> MLP (L1 fresh this launch)
        ee[k] = (pf[k] >= 0) ? g_slot[pf[k]] : 0ULL;
#pragma unroll
    for (int k = 0; k < ELEMS; k++) {
        int i = base + k;
        if (pf[k] >= 0 && (unsigned)ee[k] == BIG + (unsigned)(N - i)) {
            fmask |= 1u << k;
            s++;
        }
    }

    int lane = threadIdx.x & 31, wid = threadIdx.x >> 5;
    int x = s;
#pragma unroll
    for (int o = 1; o < 32; o <<= 1) {
        int y = __shfl_up_sync(0xFFFFFFFFu, x, o);
        if (lane >= o) x += y;
    }
    if (lane == 31) s_warp[wid] = x;
    __syncthreads();
    if (wid == 0) {
        int w = (lane < 8) ? s_warp[lane] : 0;
#pragma unroll
        for (int o = 1; o < 8; o <<= 1) {
            int y = __shfl_up_sync(0xFFFFFFFFu, w, o);
            if (lane >= o) w += y;
        }
        if (lane < 8) s_warp[lane] = w;
    }
    __syncthreads();
    int total = s_warp[7];
    int texcl = x - s + (wid > 0 ? s_warp[wid - 1] : 0);

    if (threadIdx.x == 0)
        *((volatile unsigned long long*)&g_tile[tile]) = (1ULL << 32) | (unsigned)total;

    if (wid == 0) {
        int excl = 0;
        int look = tile - 1;
        while (look >= 0) {
            int idx = look - lane;
            unsigned long long p = (idx >= 0)
                ? *((volatile unsigned long long*)&g_tile[idx])
                : (2ULL << 32);
            int st = (int)(p >> 32);
            int val = (int)(p & 0xFFFFFFFFULL);
            unsigned bp = __ballot_sync(0xFFFFFFFFu, st == 2);
            unsigned bn = __ballot_sync(0xFFFFFFFFu, st == 0);
            if (bp) {
                int j = __ffs(bp) - 1;
                unsigned need = j ? ((1u << j) - 1u) : 0u;
                if ((bn & need) == 0) {
                    int c = (lane <= j) ? val : 0;
#pragma unroll
                    for (int o = 16; o > 0; o >>= 1) c += __shfl_down_sync(0xFFFFFFFFu, c, o);
                    excl += __shfl_sync(0xFFFFFFFFu, c, 0);
                    break;
                }
            } else if (bn == 0) {
                int c = val;
#pragma unroll
                for (int o = 16; o > 0; o >>= 1) c += __shfl_down_sync(0xFFFFFFFFu, c, o);
                excl += __shfl_sync(0xFFFFFFFFu, c, 0);
                look -= 32;
            }
        }
        if (lane == 0) {
            int tot = excl + total;
            *((volatile unsigned long long*)&g_tile[tile]) = (2ULL << 32) | (unsigned)tot;
            s_prefix = excl;
            if (tile == last_tile) {
                if (build_kept) {
                    if (tot >= MAXV || hi >= N) {    // saturated or head covers all
                        g_sat = 1;
                        out[VN_OFF] = (float)(tot < MAXV ? tot : MAXV);
                    }
                } else {
                    out[VN_OFF] = (float)(tot < MAXV ? tot : MAXV);
                }
            }
        }
    }
    __syncthreads();

    int vid = s_prefix + texcl;
    int myvid[ELEMS];
#pragma unroll
    for (int k = 0; k < ELEMS; k++) {
        myvid[k] = -1;
        if (fmask & (1u << k)) {
            int slot = pf[k];
            unsigned tag = (unsigned)(ee[k] >> 32);
            int flat = (int)tag - 1;
            *((volatile unsigned long long*)&g_slot[slot]) =
                ((unsigned long long)tag << 32) | (unsigned)vid;   // unblocks spinners
            if (vid < MAXV) {
                int cx = flat % GX;
                int r = flat / GX;
                int cy = r % GY;
                int cz = r / GY;
                out[COOR_OFF + (size_t)vid * 3 + 0] = (float)cz;
                out[COOR_OFF + (size_t)vid * 3 + 1] = (float)cy;
                out[COOR_OFF + (size_t)vid * 3 + 2] = (float)cx;
                if (build_kept) {
                    unsigned long long ent =
                        ((unsigned long long)tag << 32) | (unsigned)vid;
                    unsigned h2 = hash_kept(flat);
                    volatile unsigned long long* vk = (volatile unsigned long long*)g_kept;
                    for (;;) {
                        unsigned long long cur = vk[h2];
                        if ((unsigned)(cur >> 32) == tag) break;   // stale == idempotent
                        if (cur == 0ULL) {
                            unsigned long long old = atomicCAS(&g_kept[h2], 0ULL, ent);
                            if (old == 0ULL || (unsigned)(old >> 32) == tag) break;
                        }
                        h2 = (h2 + 1) & KMASK;
                    }
                }
            }
            myvid[k] = vid;
            vid++;
        }
    }
    __threadfence();
    __syncthreads();

#pragma unroll
    for (int k = 0; k < ELEMS; k++) {
        int i = base + k;
        if (i < lo || i >= hi || pf[k] < 0) continue;
        int v = myvid[k];
        if (v < 0) {
            unsigned lo32 = (unsigned)*((volatile unsigned long long*)&g_slot[pf[k]]);
            while (lo32 >= BIG) {
                __nanosleep(60);
                lo32 = (unsigned)*((volatile unsigned long long*)&g_slot[pf[k]]);
            }
            v = (int)lo32;
        }
        if (v < MAXV) {
            int sl = atomicAdd(&g_cnt[v], 1);
            if (sl < MAXP) g_idx[v * MAXP + sl] = i;
        }
    }
}

// ---------------- kernel 1: head — init + bin (1 pt/thread) + barrier + tiles ---
__global__ void __launch_bounds__(TPB, 5) vox_head(const float* __restrict__ pts,
                                                   int N, int Nh, int nb_head,
                                                   float* __restrict__ out) {
    int tid = blockIdx.x * TPB + threadIdx.x;
    int gsz = gridDim.x * TPB;

    for (int i = tid; i < NB_MAX; i += gsz) g_tile[i] = 0ULL;
    if (tid == 0) g_sat = 0;
    for (int i = tid; i < MAXV; i += gsz) g_cnt[i] = 0;

    if (tid < Nh) {
        int i = tid;                              // exactly one point per thread
        float x = pts[(size_t)i * 5 + 0];
        float y = pts[(size_t)i * 5 + 1];
        float z = pts[(size_t)i * 5 + 2];
        int flat;
        if (!bin3(x, y, z, &flat)) {
            g_pflat[i] = -1;
        } else {
            unsigned h = claim_record(flat, BIG + (unsigned)(N - i));
            g_pflat[i] = (int)h;
        }
    }
    gbar(gridDim.x);

    if ((int)blockIdx.x < nb_head)
        fused_tile(blockIdx.x, 0, Nh, N, nb_head - 1, out, true);
}

// ---------------- kernel 2: tail — membership stream (+ in-kernel fallback) ----
#define TELEMS 4
__global__ void __launch_bounds__(TPB, 6) vox_tail(const float* __restrict__ pts,
                                                   int N, int Nh, int nb_head,
                                                   int nb_total,
                                                   float* __restrict__ out) {
    int sat = *((volatile int*)&g_sat);
    int tid = blockIdx.x * TPB + threadIdx.x;
    int gsz = gridDim.x * TPB;
    int lane = threadIdx.x & 31;
    int nwarp = gsz >> 5;
    int gw = tid >> 5;
    int nchunks = (N - Nh + 32 * TELEMS - 1) / (32 * TELEMS);

    for (int ch = gw; ch < nchunks; ch += nwarp) {
        int base = Nh + ch * (32 * TELEMS) + lane;
        float px[TELEMS], py[TELEMS], pz[TELEMS];
        int ok[TELEMS], flat[TELEMS];
#pragma unroll
        for (int k = 0; k < TELEMS; k++) {
            int i = base + k * 32;
            ok[k] = (i < N);
            if (ok[k]) {
                px[k] = __ldg(pts + (size_t)i * 5 + 0);
                py[k] = __ldg(pts + (size_t)i * 5 + 1);
                pz[k] = __ldg(pts + (size_t)i * 5 + 2);
            }
        }
#pragma unroll
        for (int k = 0; k < TELEMS; k++)
            if (ok[k]) ok[k] = bin3(px[k], py[k], pz[k], &flat[k]);

        if (sat) {
            unsigned h[TELEMS];
            unsigned long long e[TELEMS];
#pragma unroll
            for (int k = 0; k < TELEMS; k++) {
                if (ok[k]) {
                    h[k] = hash_kept(flat[k]);
                    e[k] = g_kept[h[k]];                  // batched first probes
                }
            }
#pragma unroll
            for (int k = 0; k < TELEMS; k++) {
                if (!ok[k]) continue;
                unsigned tag = (unsigned)(flat[k] + 1);
                unsigned hh = h[k];
                unsigned long long cur = e[k];
                for (;;) {
                    if (cur == 0ULL) break;               // voxel not kept
                    if ((unsigned)(cur >> 32) == tag) {
                        int v = (int)(unsigned)(cur & 0xFFFFFFFFULL);
                        int i = base + k * 32;
                        int sl = atomicAdd(&g_cnt[v], 1);
                        if (sl < MAXP) g_idx[v * MAXP + sl] = i;
                        break;
                    }
                    hh = (hh + 1) & KMASK;
                    cur = g_kept[hh];
                }
            }
        } else {
#pragma unroll
            for (int k = 0; k < TELEMS; k++) {
                int i = base + k * 32;
                if (i >= N) continue;
                if (!ok[k]) { g_pflat[i] = -1; continue; }
                unsigned hh = claim_record(flat[k], BIG + (unsigned)(N - i));
                g_pflat[i] = (int)hh;
            }
        }
    }

    if (!sat) {
        // fallback: finish scan pipeline in-kernel. All TGRID blocks co-resident;
        // block-strided tiles -> lookback targets are concurrent or done.
        gbar(gridDim.x);
        for (int t = nb_head + (int)blockIdx.x; t < nb_total; t += (int)gridDim.x) {
            fused_tile(t, Nh, N, N, nb_total - 1, out, false);
            __syncthreads();
        }
    }
}

// ---------------- kernel 3: emit — smem staging, coalesced output -------------
__global__ void __launch_bounds__(TPB) vox_emit(const float* __restrict__ pts,
                                                float* __restrict__ out) {
    __shared__ float srow[TPB * 50];          // 50 KB
    int vid = blockIdx.x * TPB + threadIdx.x;
    if (vid < MAXV) {
        int c = g_cnt[vid];
        int m = c < MAXP ? c : MAXP;
        int a[MAXP];
        for (int k = 0; k < m; k++) a[k] = g_idx[vid * MAXP + k];
        for (int k = 1; k < m; k++) {         // restores deterministic point order
            int v = a[k];
            int j = k - 1;
            while (j >= 0 && a[j] > v) { a[j + 1] = a[j]; j--; }
            a[j + 1] = v;
        }
        float* row = srow + threadIdx.x * 50;
#pragma unroll
        for (int q = 0; q < 50; q++) row[q] = 0.0f;
        for (int k = 0; k < m; k++) {
            const float* p = pts + (size_t)a[k] * 5;
            row[k * 5 + 0] = __ldg(p + 0);
            row[k * 5 + 1] = __ldg(p + 1);
            row[k * 5 + 2] = __ldg(p + 2);
            row[k * 5 + 3] = __ldg(p + 3);
            row[k * 5 + 4] = __ldg(p + 4);
        }
        out[NP_OFF + vid] = (float)m;
        if (m == 0) {                          // invalid slot -> coors = -1
            out[COOR_OFF + (size_t)vid * 3 + 0] = -1.0f;
            out[COOR_OFF + (size_t)vid * 3 + 1] = -1.0f;
            out[COOR_OFF + (size_t)vid * 3 + 2] = -1.0f;
        }
    }
    __syncthreads();
    int rows = MAXV - blockIdx.x * TPB;
    if (rows > TPB) rows = TPB;
    int nf4 = rows * 50 / 4;                   // rows even -> divisible by 4
    const float4* s4 = (const float4*)srow;
    float4* o4 = (float4*)(out + VOX_OFF + (size_t)blockIdx.x * TPB * 50);
    for (int j = threadIdx.x; j < nf4; j += TPB) o4[j] = s4[j];
}

// ---------------- launch ----------------
extern "C" void kernel_launch(void* const* d_in, const int* in_sizes, int n_in,
                              void* d_out, int out_size) {
    const float* pts = (const float*)d_in[0];
    int N = in_sizes[0] / 5;
    if (N > N_MAX) N = N_MAX;
    float* out = (float*)d_out;

    int Nh = N < M0 ? N : M0;
    int nb_head = (Nh + TILE - 1) / TILE;      // 352 for full input
    int nb_total = (N + TILE - 1) / TILE;

    vox_head<<<HGRID, TPB>>>(pts, N, Nh, nb_head, out);
    if (N > Nh)
        vox_tail<<<TGRID, TPB>>>(pts, N, Nh, nb_head, nb_total, out);
    vox_emit<<<(MAXV + TPB - 1) / TPB, TPB>>>(pts, out);
}